// round 1
// baseline (speedup 1.0000x reference)
#include <cuda_runtime.h>

// Problem constants
#define BB 4
#define TT 2048
#define EE 1024
#define HH 16
#define HD 64
#define BT (BB * TT)   // 8192 rows

// ---------------------------------------------------------------------------
// Scratch (static __device__ arrays; no runtime allocation allowed)
// ---------------------------------------------------------------------------
__device__ float g_Q[BB * HH * TT * HD];   // [b,h,t,d], q pre-scaled
__device__ float g_K[BB * HH * TT * HD];
__device__ float g_V[BB * HH * TT * HD];
__device__ float g_AO[BT * EE];            // attention output, [b,t,e]
__device__ float g_WpT[EE * EE];           // W_proj transposed: [j][e]

// ---------------------------------------------------------------------------
// Kernel 1: per-head QKV projection
//   x[B,T,E] -> per head h uses x[..., h*64:(h+1)*64]
//   qkv[b,t,h,0:192] = xh @ W_qkv[h] + b_qkv[h];  q *= softmax scale
// Block: 256 threads, tile 64 rows x 192 cols, thread tile 4x12.
// ---------------------------------------------------------------------------
__global__ __launch_bounds__(256, 1)
void qkv_kernel(const float* __restrict__ x,
                const float* __restrict__ Wq,
                const float* __restrict__ bq) {
    extern __shared__ float sm[];
    float* Xs = sm;              // [64][68]
    float* Ws = sm + 64 * 68;    // [64][196]

    const int h    = blockIdx.y;
    const int row0 = blockIdx.x * 64;     // over B*T
    const int tid  = threadIdx.x;

    for (int i = tid; i < 64 * 64; i += 256) {
        int r = i >> 6, d = i & 63;
        Xs[r * 68 + d] = x[(size_t)(row0 + r) * EE + h * HD + d];
    }
    const float* Wh = Wq + h * (64 * 192);
    for (int i = tid; i < 64 * 192; i += 256) {
        int d = i / 192, c = i - d * 192;
        Ws[d * 196 + c] = Wh[i];
    }
    __syncthreads();

    const int tx = tid & 15, ty = tid >> 4;
    const int r0 = ty * 4, c0 = tx * 12;

    float acc[4][12];
#pragma unroll
    for (int i = 0; i < 4; i++)
#pragma unroll
        for (int j = 0; j < 12; j++) acc[i][j] = 0.f;

    for (int d = 0; d < 64; d++) {
        float a[4];
#pragma unroll
        for (int i = 0; i < 4; i++) a[i] = Xs[(r0 + i) * 68 + d];
        const float4 b0 = *(const float4*)&Ws[d * 196 + c0];
        const float4 b1 = *(const float4*)&Ws[d * 196 + c0 + 4];
        const float4 b2 = *(const float4*)&Ws[d * 196 + c0 + 8];
        const float bb[12] = {b0.x, b0.y, b0.z, b0.w,
                              b1.x, b1.y, b1.z, b1.w,
                              b2.x, b2.y, b2.z, b2.w};
#pragma unroll
        for (int i = 0; i < 4; i++)
#pragma unroll
            for (int j = 0; j < 12; j++)
                acc[i][j] = fmaf(a[i], bb[j], acc[i][j]);
    }

    const float scale = (float)(1.0 / (8.0 + 1e-5));
#pragma unroll
    for (int j = 0; j < 12; j++) {
        const int c   = c0 + j;
        const int sec = c >> 6;      // 0=q, 1=k, 2=v
        const int d   = c & 63;
        const float bias = bq[h * 192 + c];
#pragma unroll
        for (int i = 0; i < 4; i++) {
            const int gr = row0 + r0 + i;        // [0, B*T)
            const int b_ = gr / TT;
            const int t  = gr - b_ * TT;
            const size_t off = ((size_t)(b_ * HH + h) * TT + t) * HD + d;
            const float v = acc[i][j] + bias;
            if (sec == 0)      g_Q[off] = v * scale;
            else if (sec == 1) g_K[off] = v;
            else               g_V[off] = v;
        }
    }
}

// ---------------------------------------------------------------------------
// Kernel 2: causal flash attention, fp32, BM=BN=64, online softmax.
// Block: 256 threads (16x16), thread tile 4x4.
// ---------------------------------------------------------------------------
__global__ __launch_bounds__(256, 1)
void attn_kernel() {
    extern __shared__ float sm[];
    float* Qs   = sm;                // [r][d]  64x68
    float* Ks   = sm + 64 * 68;      // [d][k]  transposed, 64x68
    float* Vs   = sm + 2 * 64 * 68;  // [k][d]  64x68
    float* Ss   = sm + 3 * 64 * 68;  // [r][c]  64x68 (scores, then probs)
    float* cfac = sm + 4 * 64 * 68;  // [64]

    const int bh = blockIdx.y;                       // b*H + h
    const int qt = gridDim.x - 1 - blockIdx.x;       // big tiles first
    const int q0 = qt * 64;
    const float* Qp = g_Q + (size_t)bh * TT * HD;
    const float* Kp = g_K + (size_t)bh * TT * HD;
    const float* Vp = g_V + (size_t)bh * TT * HD;

    const int tid = threadIdx.x;
    const int tx = tid & 15, ty = tid >> 4;
    const int r0 = ty * 4, c0 = tx * 4;

    for (int i = tid; i < 64 * 64; i += 256)
        Qs[(i >> 6) * 68 + (i & 63)] = Qp[q0 * 64 + i];

    float accv[4][4];
#pragma unroll
    for (int i = 0; i < 4; i++)
#pragma unroll
        for (int j = 0; j < 4; j++) accv[i][j] = 0.f;

    float m_r = -1e30f, l_r = 0.f;   // valid in threads 0..63

    for (int kt = 0; kt <= qt; kt++) {
        __syncthreads();   // previous PV done with Ss/Vs
        const int kbase = kt * 64 * 64;
        for (int i = tid; i < 64 * 64; i += 256) {
            const int k = i >> 6, d = i & 63;
            Ks[d * 68 + k] = Kp[kbase + i];
            Vs[k * 68 + d] = Vp[kbase + i];
        }
        __syncthreads();

        // S = Q K^T (q pre-scaled)
        float s[4][4];
#pragma unroll
        for (int i = 0; i < 4; i++)
#pragma unroll
            for (int j = 0; j < 4; j++) s[i][j] = 0.f;

        for (int d = 0; d < 64; d++) {
            float a[4];
#pragma unroll
            for (int i = 0; i < 4; i++) a[i] = Qs[(r0 + i) * 68 + d];
            const float4 b = *(const float4*)&Ks[d * 68 + c0];
#pragma unroll
            for (int i = 0; i < 4; i++) {
                s[i][0] = fmaf(a[i], b.x, s[i][0]);
                s[i][1] = fmaf(a[i], b.y, s[i][1]);
                s[i][2] = fmaf(a[i], b.z, s[i][2]);
                s[i][3] = fmaf(a[i], b.w, s[i][3]);
            }
        }
        if (kt == qt) {   // causal mask on diagonal tile
#pragma unroll
            for (int i = 0; i < 4; i++)
#pragma unroll
                for (int j = 0; j < 4; j++)
                    if (c0 + j > r0 + i) s[i][j] = -1e30f;
        }
#pragma unroll
        for (int i = 0; i < 4; i++)
            *(float4*)&Ss[(r0 + i) * 68 + c0] =
                make_float4(s[i][0], s[i][1], s[i][2], s[i][3]);
        __syncthreads();

        // online softmax per row (threads 0..63)
        if (tid < 64) {
            const int r = tid;
            float mx = m_r;
            for (int j = 0; j < 64; j += 4) {
                const float4 v = *(const float4*)&Ss[r * 68 + j];
                mx = fmaxf(mx, fmaxf(fmaxf(v.x, v.y), fmaxf(v.z, v.w)));
            }
            float lsum = 0.f;
            for (int j = 0; j < 64; j += 4) {
                float4 v = *(float4*)&Ss[r * 68 + j];
                v.x = __expf(v.x - mx); v.y = __expf(v.y - mx);
                v.z = __expf(v.z - mx); v.w = __expf(v.w - mx);
                lsum += (v.x + v.y) + (v.z + v.w);
                *(float4*)&Ss[r * 68 + j] = v;
            }
            const float cr = __expf(m_r - mx);
            l_r = l_r * cr + lsum;
            m_r = mx;
            cfac[r] = cr;
        }
        __syncthreads();

        // rescale accumulator, then O += P V
        float cf[4];
#pragma unroll
        for (int i = 0; i < 4; i++) cf[i] = cfac[r0 + i];
#pragma unroll
        for (int i = 0; i < 4; i++)
#pragma unroll
            for (int j = 0; j < 4; j++) accv[i][j] *= cf[i];

        for (int kk = 0; kk < 64; kk++) {
            float a[4];
#pragma unroll
            for (int i = 0; i < 4; i++) a[i] = Ss[(r0 + i) * 68 + kk];
            const float4 b = *(const float4*)&Vs[kk * 68 + c0];
#pragma unroll
            for (int i = 0; i < 4; i++) {
                accv[i][0] = fmaf(a[i], b.x, accv[i][0]);
                accv[i][1] = fmaf(a[i], b.y, accv[i][1]);
                accv[i][2] = fmaf(a[i], b.z, accv[i][2]);
                accv[i][3] = fmaf(a[i], b.w, accv[i][3]);
            }
        }
    }

    __syncthreads();
    if (tid < 64) cfac[tid] = 1.0f / l_r;
    __syncthreads();

    const int b_ = bh >> 4, h = bh & 15;
#pragma unroll
    for (int i = 0; i < 4; i++) {
        const int t = q0 + r0 + i;
        const float inv = cfac[r0 + i];
        const float4 o = make_float4(accv[i][0] * inv, accv[i][1] * inv,
                                     accv[i][2] * inv, accv[i][3] * inv);
        *(float4*)&g_AO[((size_t)(b_ * TT + t)) * EE + h * HD + c0] = o;
    }
}

// ---------------------------------------------------------------------------
// Kernel 3: transpose W_proj -> g_WpT[j][e] = W_proj[e][j]
// ---------------------------------------------------------------------------
__global__ void tr_kernel(const float* __restrict__ Wp) {
    __shared__ float tile[32][33];
    const int bx = blockIdx.x * 32, by = blockIdx.y * 32;
    const int tx = threadIdx.x, ty = threadIdx.y;   // 32x8
    for (int i = ty; i < 32; i += 8)
        tile[i][tx] = Wp[(size_t)(by + i) * EE + bx + tx];
    __syncthreads();
    for (int i = ty; i < 32; i += 8)
        g_WpT[(size_t)(bx + i) * EE + by + tx] = tile[tx][i];
}

// ---------------------------------------------------------------------------
// Kernel 4: out = g_AO @ W_proj^T + b_proj  (A[8192,1024] x WpT[1024,1024])
// Block tile 64x128, threads 256 (16x16), thread tile 4x8, k-tile 32.
// ---------------------------------------------------------------------------
__global__ __launch_bounds__(256, 1)
void proj_kernel(const float* __restrict__ bp, float* __restrict__ out) {
    __shared__ float As[64 * 36];    // [r][k]
    __shared__ float Bs[32 * 132];   // [k][c]

    const int row0 = blockIdx.x * 64;
    const int col0 = blockIdx.y * 128;
    const int tid = threadIdx.x;
    const int tx = tid & 15, ty = tid >> 4;
    const int r0 = ty * 4, c0 = tx * 8;

    float acc[4][8];
#pragma unroll
    for (int i = 0; i < 4; i++)
#pragma unroll
        for (int j = 0; j < 8; j++) acc[i][j] = 0.f;

    for (int k0 = 0; k0 < EE; k0 += 32) {
        __syncthreads();
        for (int i = tid; i < 64 * 32; i += 256) {
            const int r = i >> 5, kk = i & 31;
            As[r * 36 + kk] = g_AO[(size_t)(row0 + r) * EE + k0 + kk];
        }
        for (int i = tid; i < 32 * 128; i += 256) {
            const int kk = i >> 7, c = i & 127;
            Bs[kk * 132 + c] = g_WpT[(size_t)(k0 + kk) * EE + col0 + c];
        }
        __syncthreads();

#pragma unroll 8
        for (int kk = 0; kk < 32; kk++) {
            float a[4];
#pragma unroll
            for (int i = 0; i < 4; i++) a[i] = As[(r0 + i) * 36 + kk];
            const float4 b0 = *(const float4*)&Bs[kk * 132 + c0];
            const float4 b1 = *(const float4*)&Bs[kk * 132 + c0 + 4];
            const float bb[8] = {b0.x, b0.y, b0.z, b0.w, b1.x, b1.y, b1.z, b1.w};
#pragma unroll
            for (int i = 0; i < 4; i++)
#pragma unroll
                for (int j = 0; j < 8; j++)
                    acc[i][j] = fmaf(a[i], bb[j], acc[i][j]);
        }
    }

#pragma unroll
    for (int i = 0; i < 4; i++) {
        const int r = row0 + r0 + i;
        float4 o0, o1;
        o0.x = acc[i][0] + bp[col0 + c0 + 0];
        o0.y = acc[i][1] + bp[col0 + c0 + 1];
        o0.z = acc[i][2] + bp[col0 + c0 + 2];
        o0.w = acc[i][3] + bp[col0 + c0 + 3];
        o1.x = acc[i][4] + bp[col0 + c0 + 4];
        o1.y = acc[i][5] + bp[col0 + c0 + 5];
        o1.z = acc[i][6] + bp[col0 + c0 + 6];
        o1.w = acc[i][7] + bp[col0 + c0 + 7];
        *(float4*)&out[(size_t)r * EE + col0 + c0]     = o0;
        *(float4*)&out[(size_t)r * EE + col0 + c0 + 4] = o1;
    }
}

// ---------------------------------------------------------------------------
// Launch
// ---------------------------------------------------------------------------
extern "C" void kernel_launch(void* const* d_in, const int* in_sizes, int n_in,
                              void* d_out, int out_size) {
    const float* x  = (const float*)d_in[0];
    const float* Wq = (const float*)d_in[1];
    const float* bq = (const float*)d_in[2];
    const float* Wp = (const float*)d_in[3];
    const float* bp = (const float*)d_in[4];
    float* out = (float*)d_out;

    const int qkv_smem  = (64 * 68 + 64 * 196) * 4;        // 67584 B
    const int attn_smem = (4 * 64 * 68 + 64) * 4;          // 69888 B
    cudaFuncSetAttribute(qkv_kernel,  cudaFuncAttributeMaxDynamicSharedMemorySize, qkv_smem);
    cudaFuncSetAttribute(attn_kernel, cudaFuncAttributeMaxDynamicSharedMemorySize, attn_smem);

    qkv_kernel<<<dim3(BT / 64, HH), 256, qkv_smem>>>(x, Wq, bq);
    tr_kernel<<<dim3(EE / 32, EE / 32), dim3(32, 8)>>>(Wp);
    attn_kernel<<<dim3(TT / 64, BB * HH), 256, attn_smem>>>();
    proj_kernel<<<dim3(BT / 64, EE / 128), 256>>>(bp, out);
}

// round 3
// speedup vs baseline: 1.3550x; 1.3550x over previous
#include <cuda_runtime.h>
#include <cstdint>

// Problem constants
#define BB 4
#define TT 2048
#define EE 1024
#define HH 16
#define HD 64
#define BT (BB * TT)   // 8192 rows

// ---------------------------------------------------------------------------
// Scratch (static __device__ arrays; no runtime allocation allowed)
// ---------------------------------------------------------------------------
__device__ float g_Q[BB * HH * TT * HD];   // [b,h,t,d], q pre-scaled
__device__ float g_K[BB * HH * TT * HD];
__device__ float g_V[BB * HH * TT * HD];
__device__ float g_AO[BT * EE];            // attention output, [b,t,e]

// ---------------------------------------------------------------------------
// tf32 helpers (plain sm_100-target PTX: mma.sync is sm_80+, always valid)
// ---------------------------------------------------------------------------
__device__ __forceinline__ uint32_t f2tf32(float f) {
    uint32_t r;
    asm("cvt.rna.tf32.f32 %0, %1;" : "=r"(r) : "f"(f));
    return r;
}

// D = A(16x8, row) * B(8x8, col) + C, tf32 inputs, fp32 accum
__device__ __forceinline__ void mma_tf32_16x8x8(
    float& c0, float& c1, float& c2, float& c3,
    uint32_t a0, uint32_t a1, uint32_t a2, uint32_t a3,
    uint32_t b0, uint32_t b1) {
    asm volatile(
        "mma.sync.aligned.m16n8k8.row.col.f32.tf32.tf32.f32 "
        "{%0,%1,%2,%3}, {%4,%5,%6,%7}, {%8,%9}, {%0,%1,%2,%3};"
        : "+f"(c0), "+f"(c1), "+f"(c2), "+f"(c3)
        : "r"(a0), "r"(a1), "r"(a2), "r"(a3), "r"(b0), "r"(b1));
}

// ---------------------------------------------------------------------------
// Kernel 1: per-head QKV projection (unchanged — known correct)
// ---------------------------------------------------------------------------
__global__ __launch_bounds__(256, 1)
void qkv_kernel(const float* __restrict__ x,
                const float* __restrict__ Wq,
                const float* __restrict__ bq) {
    extern __shared__ float sm[];
    float* Xs = sm;              // [64][68]
    float* Ws = sm + 64 * 68;    // [64][196]

    const int h    = blockIdx.y;
    const int row0 = blockIdx.x * 64;     // over B*T
    const int tid  = threadIdx.x;

    for (int i = tid; i < 64 * 64; i += 256) {
        int r = i >> 6, d = i & 63;
        Xs[r * 68 + d] = x[(size_t)(row0 + r) * EE + h * HD + d];
    }
    const float* Wh = Wq + h * (64 * 192);
    for (int i = tid; i < 64 * 192; i += 256) {
        int d = i / 192, c = i - d * 192;
        Ws[d * 196 + c] = Wh[i];
    }
    __syncthreads();

    const int tx = tid & 15, ty = tid >> 4;
    const int r0 = ty * 4, c0 = tx * 12;

    float acc[4][12];
#pragma unroll
    for (int i = 0; i < 4; i++)
#pragma unroll
        for (int j = 0; j < 12; j++) acc[i][j] = 0.f;

    for (int d = 0; d < 64; d++) {
        float a[4];
#pragma unroll
        for (int i = 0; i < 4; i++) a[i] = Xs[(r0 + i) * 68 + d];
        const float4 b0 = *(const float4*)&Ws[d * 196 + c0];
        const float4 b1 = *(const float4*)&Ws[d * 196 + c0 + 4];
        const float4 b2 = *(const float4*)&Ws[d * 196 + c0 + 8];
        const float bb[12] = {b0.x, b0.y, b0.z, b0.w,
                              b1.x, b1.y, b1.z, b1.w,
                              b2.x, b2.y, b2.z, b2.w};
#pragma unroll
        for (int i = 0; i < 4; i++)
#pragma unroll
            for (int j = 0; j < 12; j++)
                acc[i][j] = fmaf(a[i], bb[j], acc[i][j]);
    }

    const float scale = (float)(1.0 / (8.0 + 1e-5));
#pragma unroll
    for (int j = 0; j < 12; j++) {
        const int c   = c0 + j;
        const int sec = c >> 6;      // 0=q, 1=k, 2=v
        const int d   = c & 63;
        const float bias = bq[h * 192 + c];
#pragma unroll
        for (int i = 0; i < 4; i++) {
            const int gr = row0 + r0 + i;        // [0, B*T)
            const int b_ = gr / TT;
            const int t  = gr - b_ * TT;
            const size_t off = ((size_t)(b_ * HH + h) * TT + t) * HD + d;
            const float v = acc[i][j] + bias;
            if (sec == 0)      g_Q[off] = v * scale;
            else if (sec == 1) g_K[off] = v;
            else               g_V[off] = v;
        }
    }
}

// ---------------------------------------------------------------------------
// Kernel 2: causal flash attention (unchanged — known correct)
// ---------------------------------------------------------------------------
__global__ __launch_bounds__(256, 1)
void attn_kernel() {
    extern __shared__ float sm[];
    float* Qs   = sm;                // [r][d]  64x68
    float* Ks   = sm + 64 * 68;      // [d][k]  transposed, 64x68
    float* Vs   = sm + 2 * 64 * 68;  // [k][d]  64x68
    float* Ss   = sm + 3 * 64 * 68;  // [r][c]  64x68 (scores, then probs)
    float* cfac = sm + 4 * 64 * 68;  // [64]

    const int bh = blockIdx.y;                       // b*H + h
    const int qt = gridDim.x - 1 - blockIdx.x;       // big tiles first
    const int q0 = qt * 64;
    const float* Qp = g_Q + (size_t)bh * TT * HD;
    const float* Kp = g_K + (size_t)bh * TT * HD;
    const float* Vp = g_V + (size_t)bh * TT * HD;

    const int tid = threadIdx.x;
    const int tx = tid & 15, ty = tid >> 4;
    const int r0 = ty * 4, c0 = tx * 4;

    for (int i = tid; i < 64 * 64; i += 256)
        Qs[(i >> 6) * 68 + (i & 63)] = Qp[q0 * 64 + i];

    float accv[4][4];
#pragma unroll
    for (int i = 0; i < 4; i++)
#pragma unroll
        for (int j = 0; j < 4; j++) accv[i][j] = 0.f;

    float m_r = -1e30f, l_r = 0.f;   // valid in threads 0..63

    for (int kt = 0; kt <= qt; kt++) {
        __syncthreads();   // previous PV done with Ss/Vs
        const int kbase = kt * 64 * 64;
        for (int i = tid; i < 64 * 64; i += 256) {
            const int k = i >> 6, d = i & 63;
            Ks[d * 68 + k] = Kp[kbase + i];
            Vs[k * 68 + d] = Vp[kbase + i];
        }
        __syncthreads();

        // S = Q K^T (q pre-scaled)
        float s[4][4];
#pragma unroll
        for (int i = 0; i < 4; i++)
#pragma unroll
            for (int j = 0; j < 4; j++) s[i][j] = 0.f;

        for (int d = 0; d < 64; d++) {
            float a[4];
#pragma unroll
            for (int i = 0; i < 4; i++) a[i] = Qs[(r0 + i) * 68 + d];
            const float4 b = *(const float4*)&Ks[d * 68 + c0];
#pragma unroll
            for (int i = 0; i < 4; i++) {
                s[i][0] = fmaf(a[i], b.x, s[i][0]);
                s[i][1] = fmaf(a[i], b.y, s[i][1]);
                s[i][2] = fmaf(a[i], b.z, s[i][2]);
                s[i][3] = fmaf(a[i], b.w, s[i][3]);
            }
        }
        if (kt == qt) {   // causal mask on diagonal tile
#pragma unroll
            for (int i = 0; i < 4; i++)
#pragma unroll
                for (int j = 0; j < 4; j++)
                    if (c0 + j > r0 + i) s[i][j] = -1e30f;
        }
#pragma unroll
        for (int i = 0; i < 4; i++)
            *(float4*)&Ss[(r0 + i) * 68 + c0] =
                make_float4(s[i][0], s[i][1], s[i][2], s[i][3]);
        __syncthreads();

        // online softmax per row (threads 0..63)
        if (tid < 64) {
            const int r = tid;
            float mx = m_r;
            for (int j = 0; j < 64; j += 4) {
                const float4 v = *(const float4*)&Ss[r * 68 + j];
                mx = fmaxf(mx, fmaxf(fmaxf(v.x, v.y), fmaxf(v.z, v.w)));
            }
            float lsum = 0.f;
            for (int j = 0; j < 64; j += 4) {
                float4 v = *(float4*)&Ss[r * 68 + j];
                v.x = __expf(v.x - mx); v.y = __expf(v.y - mx);
                v.z = __expf(v.z - mx); v.w = __expf(v.w - mx);
                lsum += (v.x + v.y) + (v.z + v.w);
                *(float4*)&Ss[r * 68 + j] = v;
            }
            const float cr = __expf(m_r - mx);
            l_r = l_r * cr + lsum;
            m_r = mx;
            cfac[r] = cr;
        }
        __syncthreads();

        // rescale accumulator, then O += P V
        float cf[4];
#pragma unroll
        for (int i = 0; i < 4; i++) cf[i] = cfac[r0 + i];
#pragma unroll
        for (int i = 0; i < 4; i++)
#pragma unroll
            for (int j = 0; j < 4; j++) accv[i][j] *= cf[i];

        for (int kk = 0; kk < 64; kk++) {
            float a[4];
#pragma unroll
            for (int i = 0; i < 4; i++) a[i] = Ss[(r0 + i) * 68 + kk];
            const float4 b = *(const float4*)&Vs[kk * 68 + c0];
#pragma unroll
            for (int i = 0; i < 4; i++) {
                accv[i][0] = fmaf(a[i], b.x, accv[i][0]);
                accv[i][1] = fmaf(a[i], b.y, accv[i][1]);
                accv[i][2] = fmaf(a[i], b.z, accv[i][2]);
                accv[i][3] = fmaf(a[i], b.w, accv[i][3]);
            }
        }
    }

    __syncthreads();
    if (tid < 64) cfac[tid] = 1.0f / l_r;
    __syncthreads();

    const int b_ = bh >> 4, h = bh & 15;
#pragma unroll
    for (int i = 0; i < 4; i++) {
        const int t = q0 + r0 + i;
        const float inv = cfac[r0 + i];
        const float4 o = make_float4(accv[i][0] * inv, accv[i][1] * inv,
                                     accv[i][2] * inv, accv[i][3] * inv);
        *(float4*)&g_AO[((size_t)(b_ * TT + t)) * EE + h * HD + c0] = o;
    }
}

// ---------------------------------------------------------------------------
// Kernel 3 (NEW): tf32 mma.sync output projection.
//   out[8192,1024] = g_AO @ W_proj^T + b_proj
//   D[m][n] = sum_k A[m][k] * B[n][k]; Wp row-major [n][k] is exactly the
//   "col" operand of mma.m16n8k8.row.col.
// Block tile 128x128, BK=32, 8 warps (2x4), each warp 64x32 via 4x4 fragments.
// ---------------------------------------------------------------------------
#define PJ_LDA 36   // 32 + 4 pad (float4-aligned, conflict-free fragments)

__global__ __launch_bounds__(256, 1)
void proj_mma_kernel(const float* __restrict__ Wp,
                     const float* __restrict__ bp,
                     float* __restrict__ out) {
    __shared__ uint32_t As[128 * PJ_LDA];   // A tile, tf32 bits, [r][k]
    __shared__ uint32_t Bs[128 * PJ_LDA];   // B tile (=Wp rows), [n][k]

    const int tid  = threadIdx.x;
    const int wid  = tid >> 5;
    const int lane = tid & 31;
    const int row0 = blockIdx.x * 128;
    const int col0 = blockIdx.y * 128;

    const int warp_m = (wid & 1) * 64;   // 0 or 64
    const int warp_n = (wid >> 1) * 32;  // 0,32,64,96

    float c[4][4][4];   // [m16][n8][frag]
#pragma unroll
    for (int m = 0; m < 4; m++)
#pragma unroll
        for (int n = 0; n < 4; n++)
#pragma unroll
            for (int f = 0; f < 4; f++) c[m][n][f] = 0.f;

    const int lrow = lane >> 2;    // 0..7
    const int lcol = lane & 3;     // 0..3

    for (int kt = 0; kt < EE / 32; kt++) {
        const int k0 = kt * 32;
        __syncthreads();
        // stage A and B tiles (each 128x32 floats; 4 float4 per thread each)
#pragma unroll
        for (int it = 0; it < 4; it++) {
            const int lin = it * 1024 + tid * 4;   // 0..4095
            const int r = lin >> 5, cc = lin & 31;
            const float4 va = *(const float4*)&g_AO[(size_t)(row0 + r) * EE + k0 + cc];
            const float4 vb = *(const float4*)&Wp  [(size_t)(col0 + r) * EE + k0 + cc];
            *(uint4*)&As[r * PJ_LDA + cc] =
                make_uint4(f2tf32(va.x), f2tf32(va.y), f2tf32(va.z), f2tf32(va.w));
            *(uint4*)&Bs[r * PJ_LDA + cc] =
                make_uint4(f2tf32(vb.x), f2tf32(vb.y), f2tf32(vb.z), f2tf32(vb.w));
        }
        __syncthreads();

#pragma unroll
        for (int ks = 0; ks < 4; ks++) {
            const int kk = ks * 8;
            uint32_t a[4][4], b[4][2];
#pragma unroll
            for (int m = 0; m < 4; m++) {
                const int ar = warp_m + m * 16 + lrow;
                a[m][0] = As[ar * PJ_LDA + kk + lcol];
                a[m][1] = As[(ar + 8) * PJ_LDA + kk + lcol];
                a[m][2] = As[ar * PJ_LDA + kk + 4 + lcol];
                a[m][3] = As[(ar + 8) * PJ_LDA + kk + 4 + lcol];
            }
#pragma unroll
            for (int n = 0; n < 4; n++) {
                const int br = warp_n + n * 8 + lrow;   // lrow = n index here
                b[n][0] = Bs[br * PJ_LDA + kk + lcol];
                b[n][1] = Bs[br * PJ_LDA + kk + 4 + lcol];
            }
#pragma unroll
            for (int m = 0; m < 4; m++)
#pragma unroll
                for (int n = 0; n < 4; n++)
                    mma_tf32_16x8x8(c[m][n][0], c[m][n][1], c[m][n][2], c[m][n][3],
                                    a[m][0], a[m][1], a[m][2], a[m][3],
                                    b[n][0], b[n][1]);
        }
    }

    // epilogue: c frag rows = lane/4 (+8), cols = 2*(lane%4) (+1)
#pragma unroll
    for (int m = 0; m < 4; m++) {
#pragma unroll
        for (int n = 0; n < 4; n++) {
            const int col = col0 + warp_n + n * 8 + 2 * lcol;
            const int r1  = row0 + warp_m + m * 16 + lrow;
            const float b0 = bp[col], b1 = bp[col + 1];
            float2 o0 = make_float2(c[m][n][0] + b0, c[m][n][1] + b1);
            float2 o1 = make_float2(c[m][n][2] + b0, c[m][n][3] + b1);
            *(float2*)&out[(size_t)r1 * EE + col]       = o0;
            *(float2*)&out[(size_t)(r1 + 8) * EE + col] = o1;
        }
    }
}

// ---------------------------------------------------------------------------
// Launch
// ---------------------------------------------------------------------------
extern "C" void kernel_launch(void* const* d_in, const int* in_sizes, int n_in,
                              void* d_out, int out_size) {
    const float* x  = (const float*)d_in[0];
    const float* Wq = (const float*)d_in[1];
    const float* bq = (const float*)d_in[2];
    const float* Wp = (const float*)d_in[3];
    const float* bp = (const float*)d_in[4];
    float* out = (float*)d_out;

    const int qkv_smem  = (64 * 68 + 64 * 196) * 4;        // 67584 B
    const int attn_smem = (4 * 64 * 68 + 64) * 4;          // 69888 B
    cudaFuncSetAttribute(qkv_kernel,  cudaFuncAttributeMaxDynamicSharedMemorySize, qkv_smem);
    cudaFuncSetAttribute(attn_kernel, cudaFuncAttributeMaxDynamicSharedMemorySize, attn_smem);

    qkv_kernel<<<dim3(BT / 64, HH), 256, qkv_smem>>>(x, Wq, bq);
    attn_kernel<<<dim3(TT / 64, BB * HH), 256, attn_smem>>>();
    proj_mma_kernel<<<dim3(BT / 128, EE / 128), 256>>>(Wp, bp, out);
}

// round 6
// speedup vs baseline: 2.8349x; 2.0922x over previous
#include <cuda_runtime.h>
#include <cstdint>

// Problem constants
#define BB 4
#define TT 2048
#define EE 1024
#define HH 16
#define HD 64
#define BT (BB * TT)   // 8192 rows

// ---------------------------------------------------------------------------
// Scratch (static __device__ arrays; no runtime allocation allowed)
// ---------------------------------------------------------------------------
__device__ float g_Q[BB * HH * TT * HD];   // [b,h,t,d], q pre-scaled
__device__ float g_K[BB * HH * TT * HD];
__device__ float g_V[BB * HH * TT * HD];
__device__ float g_AO[BT * EE];            // attention output, [b,t,e]

// ---------------------------------------------------------------------------
// tf32 helpers (plain sm_100-target PTX: mma.sync is sm_80+, always valid)
// ---------------------------------------------------------------------------
__device__ __forceinline__ uint32_t f2tf32(float f) {
    uint32_t r;
    asm("cvt.rna.tf32.f32 %0, %1;" : "=r"(r) : "f"(f));
    return r;
}

// D = A(16x8, row) * B(8x8, col) + C, tf32 inputs, fp32 accum
__device__ __forceinline__ void mma_tf32_16x8x8(
    float& c0, float& c1, float& c2, float& c3,
    uint32_t a0, uint32_t a1, uint32_t a2, uint32_t a3,
    uint32_t b0, uint32_t b1) {
    asm volatile(
        "mma.sync.aligned.m16n8k8.row.col.f32.tf32.tf32.f32 "
        "{%0,%1,%2,%3}, {%4,%5,%6,%7}, {%8,%9}, {%0,%1,%2,%3};"
        : "+f"(c0), "+f"(c1), "+f"(c2), "+f"(c3)
        : "r"(a0), "r"(a1), "r"(a2), "r"(a3), "r"(b0), "r"(b1));
}

// ---------------------------------------------------------------------------
// Kernel 1: per-head QKV projection (unchanged — known correct)
// ---------------------------------------------------------------------------
__global__ __launch_bounds__(256, 1)
void qkv_kernel(const float* __restrict__ x,
                const float* __restrict__ Wq,
                const float* __restrict__ bq) {
    extern __shared__ float sm[];
    float* Xs = sm;              // [64][68]
    float* Ws = sm + 64 * 68;    // [64][196]

    const int h    = blockIdx.y;
    const int row0 = blockIdx.x * 64;     // over B*T
    const int tid  = threadIdx.x;

    for (int i = tid; i < 64 * 64; i += 256) {
        int r = i >> 6, d = i & 63;
        Xs[r * 68 + d] = x[(size_t)(row0 + r) * EE + h * HD + d];
    }
    const float* Wh = Wq + h * (64 * 192);
    for (int i = tid; i < 64 * 192; i += 256) {
        int d = i / 192, c = i - d * 192;
        Ws[d * 196 + c] = Wh[i];
    }
    __syncthreads();

    const int tx = tid & 15, ty = tid >> 4;
    const int r0 = ty * 4, c0 = tx * 12;

    float acc[4][12];
#pragma unroll
    for (int i = 0; i < 4; i++)
#pragma unroll
        for (int j = 0; j < 12; j++) acc[i][j] = 0.f;

    for (int d = 0; d < 64; d++) {
        float a[4];
#pragma unroll
        for (int i = 0; i < 4; i++) a[i] = Xs[(r0 + i) * 68 + d];
        const float4 b0 = *(const float4*)&Ws[d * 196 + c0];
        const float4 b1 = *(const float4*)&Ws[d * 196 + c0 + 4];
        const float4 b2 = *(const float4*)&Ws[d * 196 + c0 + 8];
        const float bb[12] = {b0.x, b0.y, b0.z, b0.w,
                              b1.x, b1.y, b1.z, b1.w,
                              b2.x, b2.y, b2.z, b2.w};
#pragma unroll
        for (int i = 0; i < 4; i++)
#pragma unroll
            for (int j = 0; j < 12; j++)
                acc[i][j] = fmaf(a[i], bb[j], acc[i][j]);
    }

    const float scale = (float)(1.0 / (8.0 + 1e-5));
#pragma unroll
    for (int j = 0; j < 12; j++) {
        const int c   = c0 + j;
        const int sec = c >> 6;      // 0=q, 1=k, 2=v
        const int d   = c & 63;
        const float bias = bq[h * 192 + c];
#pragma unroll
        for (int i = 0; i < 4; i++) {
            const int gr = row0 + r0 + i;        // [0, B*T)
            const int b_ = gr / TT;
            const int t  = gr - b_ * TT;
            const size_t off = ((size_t)(b_ * HH + h) * TT + t) * HD + d;
            const float v = acc[i][j] + bias;
            if (sec == 0)      g_Q[off] = v * scale;
            else if (sec == 1) g_K[off] = v;
            else               g_V[off] = v;
        }
    }
}

// ---------------------------------------------------------------------------
// Kernel 2: tf32 mma.sync causal flash attention.
//   Block: 128 threads = 4 warps; BM=64 (16 q-rows per warp), BN=64, HD=64.
//   Q fragments register-resident; softmax in registers via quad shuffles;
//   P round-trips through per-warp smem (reusing the Q staging buffer);
//   V staged [c][d] with stride 72 -> conflict-free transposed B-frag reads.
// ---------------------------------------------------------------------------
#define AT_LDQ 68   // Qs / P stride (uint32 elems)
#define AT_LDK 68   // Ks stride
#define AT_LDV 72   // Vs stride
#define AT_SMEM ((64 * AT_LDQ + 64 * AT_LDK + 64 * AT_LDV) * 4)   // 53248 B

__global__ __launch_bounds__(128, 4)
void attn_mma_kernel() {
    extern __shared__ uint32_t asm_[];
    uint32_t* Qs = asm_;                          // 64 x 68 (Q tile, later P)
    uint32_t* Ks = Qs + 64 * AT_LDQ;              // 64 x 68, [c][d]
    uint32_t* Vs = Ks + 64 * AT_LDK;              // 64 x 72, [c][d]

    const int bh = blockIdx.y;
    const int qt = gridDim.x - 1 - blockIdx.x;    // big tiles first
    const int q0 = qt * 64;
    const float* Qp = g_Q + (size_t)bh * TT * HD;
    const float* Kp = g_K + (size_t)bh * TT * HD;
    const float* Vp = g_V + (size_t)bh * TT * HD;

    const int tid  = threadIdx.x;
    const int wid  = tid >> 5;
    const int lane = tid & 31;
    const int lrow = lane >> 2;    // 0..7
    const int lcol = lane & 3;     // 0..3
    const int wm   = wid * 16;     // warp's row base within tile

    // ---- stage Q tile (tf32) and load fragments into registers ----
#pragma unroll
    for (int it = 0; it < 8; it++) {
        const int i = it * 512 + tid * 4;         // 0..4095
        const int r = i >> 6, d = i & 63;
        const float4 v = *(const float4*)&Qp[(size_t)(q0 + r) * HD + d];
        *(uint4*)&Qs[r * AT_LDQ + d] =
            make_uint4(f2tf32(v.x), f2tf32(v.y), f2tf32(v.z), f2tf32(v.w));
    }
    __syncthreads();

    uint32_t qf[8][4];
#pragma unroll
    for (int ks = 0; ks < 8; ks++) {
        const int base = (wm + lrow) * AT_LDQ + ks * 8 + lcol;
        qf[ks][0] = Qs[base];
        qf[ks][1] = Qs[base + 8 * AT_LDQ];
        qf[ks][2] = Qs[base + 4];
        qf[ks][3] = Qs[base + 8 * AT_LDQ + 4];
    }
    __syncthreads();   // Qs becomes the P buffer from here on

    float o[8][4];
#pragma unroll
    for (int n = 0; n < 8; n++)
#pragma unroll
        for (int f = 0; f < 4; f++) o[n][f] = 0.f;
    float m0 = -1e30f, m1 = -1e30f, l0 = 0.f, l1 = 0.f;

    const int r0g = q0 + wm + lrow;     // global row of frag-half 0
    const int r1g = r0g + 8;

    for (int kt = 0; kt <= qt; kt++) {
        const int kbase = kt * 64;
        __syncthreads();               // prev PV done with Ks/Vs
#pragma unroll
        for (int it = 0; it < 8; it++) {
            const int i = it * 512 + tid * 4;
            const int r = i >> 6, d = i & 63;
            const float4 kv = *(const float4*)&Kp[(size_t)(kbase + r) * HD + d];
            const float4 vv = *(const float4*)&Vp[(size_t)(kbase + r) * HD + d];
            *(uint4*)&Ks[r * AT_LDK + d] =
                make_uint4(f2tf32(kv.x), f2tf32(kv.y), f2tf32(kv.z), f2tf32(kv.w));
            *(uint4*)&Vs[r * AT_LDV + d] =
                make_uint4(f2tf32(vv.x), f2tf32(vv.y), f2tf32(vv.z), f2tf32(vv.w));
        }
        __syncthreads();

        // ---- S = Q K^T ----
        float s[8][4];
#pragma unroll
        for (int n = 0; n < 8; n++)
#pragma unroll
            for (int f = 0; f < 4; f++) s[n][f] = 0.f;

#pragma unroll
        for (int ks = 0; ks < 8; ks++) {
            const int kk = ks * 8;
#pragma unroll
            for (int n = 0; n < 8; n++) {
                const int kr = (n * 8 + lrow) * AT_LDK + kk + lcol;
                const uint32_t b0 = Ks[kr];
                const uint32_t b1 = Ks[kr + 4];
                mma_tf32_16x8x8(s[n][0], s[n][1], s[n][2], s[n][3],
                                qf[ks][0], qf[ks][1], qf[ks][2], qf[ks][3],
                                b0, b1);
            }
        }

        if (kt == qt) {   // causal mask on diagonal tile
#pragma unroll
            for (int n = 0; n < 8; n++) {
                const int cg = kbase + n * 8 + 2 * lcol;
                if (cg     > r0g) s[n][0] = -1e30f;
                if (cg + 1 > r0g) s[n][1] = -1e30f;
                if (cg     > r1g) s[n][2] = -1e30f;
                if (cg + 1 > r1g) s[n][3] = -1e30f;
            }
        }

        // ---- online softmax (register + quad shuffle) ----
        float mx0 = m0, mx1 = m1;
#pragma unroll
        for (int n = 0; n < 8; n++) {
            mx0 = fmaxf(mx0, fmaxf(s[n][0], s[n][1]));
            mx1 = fmaxf(mx1, fmaxf(s[n][2], s[n][3]));
        }
        mx0 = fmaxf(mx0, __shfl_xor_sync(0xffffffffu, mx0, 1));
        mx0 = fmaxf(mx0, __shfl_xor_sync(0xffffffffu, mx0, 2));
        mx1 = fmaxf(mx1, __shfl_xor_sync(0xffffffffu, mx1, 1));
        mx1 = fmaxf(mx1, __shfl_xor_sync(0xffffffffu, mx1, 2));

        float sum0 = 0.f, sum1 = 0.f;
#pragma unroll
        for (int n = 0; n < 8; n++) {
            s[n][0] = __expf(s[n][0] - mx0);
            s[n][1] = __expf(s[n][1] - mx0);
            s[n][2] = __expf(s[n][2] - mx1);
            s[n][3] = __expf(s[n][3] - mx1);
            sum0 += s[n][0] + s[n][1];
            sum1 += s[n][2] + s[n][3];
        }
        sum0 += __shfl_xor_sync(0xffffffffu, sum0, 1);
        sum0 += __shfl_xor_sync(0xffffffffu, sum0, 2);
        sum1 += __shfl_xor_sync(0xffffffffu, sum1, 1);
        sum1 += __shfl_xor_sync(0xffffffffu, sum1, 2);

        const float cf0 = __expf(m0 - mx0);
        const float cf1 = __expf(m1 - mx1);
        l0 = l0 * cf0 + sum0;  m0 = mx0;
        l1 = l1 * cf1 + sum1;  m1 = mx1;
#pragma unroll
        for (int n = 0; n < 8; n++) {
            o[n][0] *= cf0; o[n][1] *= cf0;
            o[n][2] *= cf1; o[n][3] *= cf1;
        }

        // ---- P -> smem (per-warp region of Qs), then PV mma ----
#pragma unroll
        for (int n = 0; n < 8; n++) {
            const int pr = (wm + lrow) * AT_LDQ + n * 8 + 2 * lcol;
            *(uint2*)&Qs[pr] = make_uint2(f2tf32(s[n][0]), f2tf32(s[n][1]));
            *(uint2*)&Qs[pr + 8 * AT_LDQ] = make_uint2(f2tf32(s[n][2]), f2tf32(s[n][3]));
        }
        __syncwarp();

#pragma unroll
        for (int ks = 0; ks < 8; ks++) {
            const int kk = ks * 8;
            const int pb = (wm + lrow) * AT_LDQ + kk + lcol;
            const uint32_t a0 = Qs[pb];
            const uint32_t a1 = Qs[pb + 8 * AT_LDQ];
            const uint32_t a2 = Qs[pb + 4];
            const uint32_t a3 = Qs[pb + 8 * AT_LDQ + 4];
#pragma unroll
            for (int n = 0; n < 8; n++) {
                const uint32_t b0 = Vs[(kk + lcol) * AT_LDV + n * 8 + lrow];
                const uint32_t b1 = Vs[(kk + 4 + lcol) * AT_LDV + n * 8 + lrow];
                mma_tf32_16x8x8(o[n][0], o[n][1], o[n][2], o[n][3],
                                a0, a1, a2, a3, b0, b1);
            }
        }
        __syncwarp();
    }

    // ---- normalize and store ----
    const float inv0 = 1.0f / l0;
    const float inv1 = 1.0f / l1;
    const int b_ = bh >> 4, h = bh & 15;
    const size_t rowbase0 = (size_t)(b_ * TT + r0g) * EE + h * HD;
    const size_t rowbase1 = (size_t)(b_ * TT + r1g) * EE + h * HD;
#pragma unroll
    for (int n = 0; n < 8; n++) {
        const int d = n * 8 + 2 * lcol;
        *(float2*)&g_AO[rowbase0 + d] = make_float2(o[n][0] * inv0, o[n][1] * inv0);
        *(float2*)&g_AO[rowbase1 + d] = make_float2(o[n][2] * inv1, o[n][3] * inv1);
    }
}

// ---------------------------------------------------------------------------
// Kernel 3: tf32 mma.sync output projection (unchanged — known correct)
// ---------------------------------------------------------------------------
#define PJ_LDA 36   // 32 + 4 pad (float4-aligned, conflict-free fragments)

__global__ __launch_bounds__(256, 1)
void proj_mma_kernel(const float* __restrict__ Wp,
                     const float* __restrict__ bp,
                     float* __restrict__ out) {
    __shared__ uint32_t As[128 * PJ_LDA];   // A tile, tf32 bits, [r][k]
    __shared__ uint32_t Bs[128 * PJ_LDA];   // B tile (=Wp rows), [n][k]

    const int tid  = threadIdx.x;
    const int wid  = tid >> 5;
    const int lane = tid & 31;
    const int row0 = blockIdx.x * 128;
    const int col0 = blockIdx.y * 128;

    const int warp_m = (wid & 1) * 64;   // 0 or 64
    const int warp_n = (wid >> 1) * 32;  // 0,32,64,96

    float c[4][4][4];   // [m16][n8][frag]
#pragma unroll
    for (int m = 0; m < 4; m++)
#pragma unroll
        for (int n = 0; n < 4; n++)
#pragma unroll
            for (int f = 0; f < 4; f++) c[m][n][f] = 0.f;

    const int lrow = lane >> 2;    // 0..7
    const int lcol = lane & 3;     // 0..3

    for (int kt = 0; kt < EE / 32; kt++) {
        const int k0 = kt * 32;
        __syncthreads();
        // stage A and B tiles (each 128x32 floats; 4 float4 per thread each)
#pragma unroll
        for (int it = 0; it < 4; it++) {
            const int lin = it * 1024 + tid * 4;   // 0..4095
            const int r = lin >> 5, cc = lin & 31;
            const float4 va = *(const float4*)&g_AO[(size_t)(row0 + r) * EE + k0 + cc];
            const float4 vb = *(const float4*)&Wp  [(size_t)(col0 + r) * EE + k0 + cc];
            *(uint4*)&As[r * PJ_LDA + cc] =
                make_uint4(f2tf32(va.x), f2tf32(va.y), f2tf32(va.z), f2tf32(va.w));
            *(uint4*)&Bs[r * PJ_LDA + cc] =
                make_uint4(f2tf32(vb.x), f2tf32(vb.y), f2tf32(vb.z), f2tf32(vb.w));
        }
        __syncthreads();

#pragma unroll
        for (int ks = 0; ks < 4; ks++) {
            const int kk = ks * 8;
            uint32_t a[4][4], b[4][2];
#pragma unroll
            for (int m = 0; m < 4; m++) {
                const int ar = warp_m + m * 16 + lrow;
                a[m][0] = As[ar * PJ_LDA + kk + lcol];
                a[m][1] = As[(ar + 8) * PJ_LDA + kk + lcol];
                a[m][2] = As[ar * PJ_LDA + kk + 4 + lcol];
                a[m][3] = As[(ar + 8) * PJ_LDA + kk + 4 + lcol];
            }
#pragma unroll
            for (int n = 0; n < 4; n++) {
                const int br = warp_n + n * 8 + lrow;
                b[n][0] = Bs[br * PJ_LDA + kk + lcol];
                b[n][1] = Bs[br * PJ_LDA + kk + 4 + lcol];
            }
#pragma unroll
            for (int m = 0; m < 4; m++)
#pragma unroll
                for (int n = 0; n < 4; n++)
                    mma_tf32_16x8x8(c[m][n][0], c[m][n][1], c[m][n][2], c[m][n][3],
                                    a[m][0], a[m][1], a[m][2], a[m][3],
                                    b[n][0], b[n][1]);
        }
    }

    // epilogue: c frag rows = lane/4 (+8), cols = 2*(lane%4) (+1)
#pragma unroll
    for (int m = 0; m < 4; m++) {
#pragma unroll
        for (int n = 0; n < 4; n++) {
            const int col = col0 + warp_n + n * 8 + 2 * lcol;
            const int r1  = row0 + warp_m + m * 16 + lrow;
            const float b0 = bp[col], b1 = bp[col + 1];
            float2 o0 = make_float2(c[m][n][0] + b0, c[m][n][1] + b1);
            float2 o1 = make_float2(c[m][n][2] + b0, c[m][n][3] + b1);
            *(float2*)&out[(size_t)r1 * EE + col]       = o0;
            *(float2*)&out[(size_t)(r1 + 8) * EE + col] = o1;
        }
    }
}

// ---------------------------------------------------------------------------
// Launch
// ---------------------------------------------------------------------------
extern "C" void kernel_launch(void* const* d_in, const int* in_sizes, int n_in,
                              void* d_out, int out_size) {
    const float* x  = (const float*)d_in[0];
    const float* Wq = (const float*)d_in[1];
    const float* bq = (const float*)d_in[2];
    const float* Wp = (const float*)d_in[3];
    const float* bp = (const float*)d_in[4];
    float* out = (float*)d_out;

    const int qkv_smem = (64 * 68 + 64 * 196) * 4;        // 67584 B
    cudaFuncSetAttribute(qkv_kernel,      cudaFuncAttributeMaxDynamicSharedMemorySize, qkv_smem);
    cudaFuncSetAttribute(attn_mma_kernel, cudaFuncAttributeMaxDynamicSharedMemorySize, AT_SMEM);

    qkv_kernel<<<dim3(BT / 64, HH), 256, qkv_smem>>>(x, Wq, bq);
    attn_mma_kernel<<<dim3(TT / 64, BB * HH), 128, AT_SMEM>>>();
    proj_mma_kernel<<<dim3(BT / 128, EE / 128), 256>>>(Wp, bp, out);
}

// round 7
// speedup vs baseline: 3.6534x; 1.2887x over previous
#include <cuda_runtime.h>
#include <cstdint>

// Problem constants
#define BB 4
#define TT 2048
#define EE 1024
#define HH 16
#define HD 64
#define BT (BB * TT)   // 8192 rows

// ---------------------------------------------------------------------------
// Scratch (static __device__ arrays; no runtime allocation allowed)
// ---------------------------------------------------------------------------
__device__ float g_Q[BB * HH * TT * HD];   // [b,h,t,d], q pre-scaled
__device__ float g_K[BB * HH * TT * HD];
__device__ float g_V[BB * HH * TT * HD];
__device__ float g_AO[BT * EE];            // attention output, [b,t,e]

// ---------------------------------------------------------------------------
// tf32 helpers (plain sm_100-target PTX: mma.sync is sm_80+, always valid)
// ---------------------------------------------------------------------------
__device__ __forceinline__ uint32_t f2tf32(float f) {
    uint32_t r;
    asm("cvt.rna.tf32.f32 %0, %1;" : "=r"(r) : "f"(f));
    return r;
}

// D = A(16x8, row) * B(8x8, col) + C, tf32 inputs, fp32 accum
__device__ __forceinline__ void mma_tf32_16x8x8(
    float& c0, float& c1, float& c2, float& c3,
    uint32_t a0, uint32_t a1, uint32_t a2, uint32_t a3,
    uint32_t b0, uint32_t b1) {
    asm volatile(
        "mma.sync.aligned.m16n8k8.row.col.f32.tf32.tf32.f32 "
        "{%0,%1,%2,%3}, {%4,%5,%6,%7}, {%8,%9}, {%0,%1,%2,%3};"
        : "+f"(c0), "+f"(c1), "+f"(c2), "+f"(c3)
        : "r"(a0), "r"(a1), "r"(a2), "r"(a3), "r"(b0), "r"(b1));
}

// ---------------------------------------------------------------------------
// Kernel 1 (NEW): tf32 mma.sync per-head QKV projection.
//   Per head h: out[BT,192] = X_h[BT,64] @ W_h[64,192], + bias, q *= scale.
//   Block: 256 threads / 8 warps (2x4); 128 rows x 192 cols; K=64 all in smem.
//   Warp tile 64x48 = 4 m16-tiles x 6 n8-tiles.
//   Ws staged transposed [n][k] stride 68 -> conflict-free B-fragment reads.
// ---------------------------------------------------------------------------
#define QK_LD   68
#define QK_SMEM ((128 * QK_LD + 192 * QK_LD) * 4)   // 87040 B (dynamic)

__global__ __launch_bounds__(256, 1)
void qkv_mma_kernel(const float* __restrict__ x,
                    const float* __restrict__ Wq,
                    const float* __restrict__ bq) {
    extern __shared__ uint32_t qsm[];
    uint32_t* Xs = qsm;                   // [128][68], [r][k]
    uint32_t* Ws = qsm + 128 * QK_LD;     // [192][68], [n][k]  (transposed W)

    const int h    = blockIdx.y;
    const int row0 = blockIdx.x * 128;    // over B*T
    const int tid  = threadIdx.x;
    const int wid  = tid >> 5;
    const int lane = tid & 31;
    const int lrow = lane >> 2;           // 0..7
    const int lcol = lane & 3;            // 0..3

    const int warp_m = (wid & 1) * 64;    // 0 or 64
    const int warp_n = (wid >> 1) * 48;   // 0,48,96,144

    // ---- stage X tile [128][64] (tf32), coalesced float4 ----
#pragma unroll
    for (int it = 0; it < 8; it++) {
        const int i = it * 256 + tid;     // 0..2047 float4s
        const int r = i >> 4, c = (i & 15) * 4;
        const float4 v = *(const float4*)&x[(size_t)(row0 + r) * EE + h * HD + c];
        *(uint4*)&Xs[r * QK_LD + c] =
            make_uint4(f2tf32(v.x), f2tf32(v.y), f2tf32(v.z), f2tf32(v.w));
    }

    // ---- stage W transposed: Ws[c][d] = Wq[h][d][c] (tf32) ----
    const float* Wh = Wq + (size_t)h * 64 * 192;
#pragma unroll
    for (int it = 0; it < 12; it++) {
        const int i = it * 256 + tid;     // 0..3071 float4s
        const int d = i / 48, c = (i % 48) * 4;
        const float4 v = *(const float4*)&Wh[d * 192 + c];
        Ws[(c + 0) * QK_LD + d] = f2tf32(v.x);
        Ws[(c + 1) * QK_LD + d] = f2tf32(v.y);
        Ws[(c + 2) * QK_LD + d] = f2tf32(v.z);
        Ws[(c + 3) * QK_LD + d] = f2tf32(v.w);
    }
    __syncthreads();

    // ---- mma over K=64 (8 k-steps), warp tile 64x48 ----
    float c[4][6][4];
#pragma unroll
    for (int m = 0; m < 4; m++)
#pragma unroll
        for (int n = 0; n < 6; n++)
#pragma unroll
            for (int f = 0; f < 4; f++) c[m][n][f] = 0.f;

#pragma unroll
    for (int ks = 0; ks < 8; ks++) {
        const int kk = ks * 8;
        uint32_t a[4][4], b[6][2];
#pragma unroll
        for (int m = 0; m < 4; m++) {
            const int ar = warp_m + m * 16 + lrow;
            a[m][0] = Xs[ar * QK_LD + kk + lcol];
            a[m][1] = Xs[(ar + 8) * QK_LD + kk + lcol];
            a[m][2] = Xs[ar * QK_LD + kk + 4 + lcol];
            a[m][3] = Xs[(ar + 8) * QK_LD + kk + 4 + lcol];
        }
#pragma unroll
        for (int n = 0; n < 6; n++) {
            const int br = warp_n + n * 8 + lrow;
            b[n][0] = Ws[br * QK_LD + kk + lcol];
            b[n][1] = Ws[br * QK_LD + kk + 4 + lcol];
        }
#pragma unroll
        for (int m = 0; m < 4; m++)
#pragma unroll
            for (int n = 0; n < 6; n++)
                mma_tf32_16x8x8(c[m][n][0], c[m][n][1], c[m][n][2], c[m][n][3],
                                a[m][0], a[m][1], a[m][2], a[m][3],
                                b[n][0], b[n][1]);
    }

    // ---- epilogue: bias, q-scale, scatter to g_Q/g_K/g_V ----
    const float scale = (float)(1.0 / (8.0 + 1e-5));
#pragma unroll
    for (int n = 0; n < 6; n++) {
        const int col = warp_n + n * 8 + 2 * lcol;   // 0..191
        const int sec = col >> 6;                    // 0=q,1=k,2=v
        const int d   = col & 63;
        const float b0 = bq[h * 192 + col];
        const float b1 = bq[h * 192 + col + 1];
        float* dst = (sec == 0) ? g_Q : (sec == 1) ? g_K : g_V;
        const float mul = (sec == 0) ? scale : 1.0f;
#pragma unroll
        for (int m = 0; m < 4; m++) {
            const int r  = row0 + warp_m + m * 16 + lrow;
            const int b_ = r / TT;
            const int t  = r - b_ * TT;
            const size_t off = ((size_t)(b_ * HH + h) * TT + t) * HD + d;
            *(float2*)&dst[off] =
                make_float2((c[m][n][0] + b0) * mul, (c[m][n][1] + b1) * mul);
            const size_t off2 = off + (size_t)8 * HD;   // row r+8, same b_ (128 | TT)
            *(float2*)&dst[off2] =
                make_float2((c[m][n][2] + b0) * mul, (c[m][n][3] + b1) * mul);
        }
    }
}

// ---------------------------------------------------------------------------
// Kernel 2: tf32 mma.sync causal flash attention (unchanged — known correct)
// ---------------------------------------------------------------------------
#define AT_LDQ 68   // Qs / P stride (uint32 elems)
#define AT_LDK 68   // Ks stride
#define AT_LDV 72   // Vs stride
#define AT_SMEM ((64 * AT_LDQ + 64 * AT_LDK + 64 * AT_LDV) * 4)   // 53248 B

__global__ __launch_bounds__(128, 4)
void attn_mma_kernel() {
    extern __shared__ uint32_t asm_[];
    uint32_t* Qs = asm_;                          // 64 x 68 (Q tile, later P)
    uint32_t* Ks = Qs + 64 * AT_LDQ;              // 64 x 68, [c][d]
    uint32_t* Vs = Ks + 64 * AT_LDK;              // 64 x 72, [c][d]

    const int bh = blockIdx.y;
    const int qt = gridDim.x - 1 - blockIdx.x;    // big tiles first
    const int q0 = qt * 64;
    const float* Qp = g_Q + (size_t)bh * TT * HD;
    const float* Kp = g_K + (size_t)bh * TT * HD;
    const float* Vp = g_V + (size_t)bh * TT * HD;

    const int tid  = threadIdx.x;
    const int wid  = tid >> 5;
    const int lane = tid & 31;
    const int lrow = lane >> 2;    // 0..7
    const int lcol = lane & 3;     // 0..3
    const int wm   = wid * 16;     // warp's row base within tile

    // ---- stage Q tile (tf32) and load fragments into registers ----
#pragma unroll
    for (int it = 0; it < 8; it++) {
        const int i = it * 512 + tid * 4;         // 0..4095
        const int r = i >> 6, d = i & 63;
        const float4 v = *(const float4*)&Qp[(size_t)(q0 + r) * HD + d];
        *(uint4*)&Qs[r * AT_LDQ + d] =
            make_uint4(f2tf32(v.x), f2tf32(v.y), f2tf32(v.z), f2tf32(v.w));
    }
    __syncthreads();

    uint32_t qf[8][4];
#pragma unroll
    for (int ks = 0; ks < 8; ks++) {
        const int base = (wm + lrow) * AT_LDQ + ks * 8 + lcol;
        qf[ks][0] = Qs[base];
        qf[ks][1] = Qs[base + 8 * AT_LDQ];
        qf[ks][2] = Qs[base + 4];
        qf[ks][3] = Qs[base + 8 * AT_LDQ + 4];
    }
    __syncthreads();   // Qs becomes the P buffer from here on

    float o[8][4];
#pragma unroll
    for (int n = 0; n < 8; n++)
#pragma unroll
        for (int f = 0; f < 4; f++) o[n][f] = 0.f;
    float m0 = -1e30f, m1 = -1e30f, l0 = 0.f, l1 = 0.f;

    const int r0g = q0 + wm + lrow;     // global row of frag-half 0
    const int r1g = r0g + 8;

    for (int kt = 0; kt <= qt; kt++) {
        const int kbase = kt * 64;
        __syncthreads();               // prev PV done with Ks/Vs
#pragma unroll
        for (int it = 0; it < 8; it++) {
            const int i = it * 512 + tid * 4;
            const int r = i >> 6, d = i & 63;
            const float4 kv = *(const float4*)&Kp[(size_t)(kbase + r) * HD + d];
            const float4 vv = *(const float4*)&Vp[(size_t)(kbase + r) * HD + d];
            *(uint4*)&Ks[r * AT_LDK + d] =
                make_uint4(f2tf32(kv.x), f2tf32(kv.y), f2tf32(kv.z), f2tf32(kv.w));
            *(uint4*)&Vs[r * AT_LDV + d] =
                make_uint4(f2tf32(vv.x), f2tf32(vv.y), f2tf32(vv.z), f2tf32(vv.w));
        }
        __syncthreads();

        // ---- S = Q K^T ----
        float s[8][4];
#pragma unroll
        for (int n = 0; n < 8; n++)
#pragma unroll
            for (int f = 0; f < 4; f++) s[n][f] = 0.f;

#pragma unroll
        for (int ks = 0; ks < 8; ks++) {
            const int kk = ks * 8;
#pragma unroll
            for (int n = 0; n < 8; n++) {
                const int kr = (n * 8 + lrow) * AT_LDK + kk + lcol;
                const uint32_t b0 = Ks[kr];
                const uint32_t b1 = Ks[kr + 4];
                mma_tf32_16x8x8(s[n][0], s[n][1], s[n][2], s[n][3],
                                qf[ks][0], qf[ks][1], qf[ks][2], qf[ks][3],
                                b0, b1);
            }
        }

        if (kt == qt) {   // causal mask on diagonal tile
#pragma unroll
            for (int n = 0; n < 8; n++) {
                const int cg = kbase + n * 8 + 2 * lcol;
                if (cg     > r0g) s[n][0] = -1e30f;
                if (cg + 1 > r0g) s[n][1] = -1e30f;
                if (cg     > r1g) s[n][2] = -1e30f;
                if (cg + 1 > r1g) s[n][3] = -1e30f;
            }
        }

        // ---- online softmax (register + quad shuffle) ----
        float mx0 = m0, mx1 = m1;
#pragma unroll
        for (int n = 0; n < 8; n++) {
            mx0 = fmaxf(mx0, fmaxf(s[n][0], s[n][1]));
            mx1 = fmaxf(mx1, fmaxf(s[n][2], s[n][3]));
        }
        mx0 = fmaxf(mx0, __shfl_xor_sync(0xffffffffu, mx0, 1));
        mx0 = fmaxf(mx0, __shfl_xor_sync(0xffffffffu, mx0, 2));
        mx1 = fmaxf(mx1, __shfl_xor_sync(0xffffffffu, mx1, 1));
        mx1 = fmaxf(mx1, __shfl_xor_sync(0xffffffffu, mx1, 2));

        float sum0 = 0.f, sum1 = 0.f;
#pragma unroll
        for (int n = 0; n < 8; n++) {
            s[n][0] = __expf(s[n][0] - mx0);
            s[n][1] = __expf(s[n][1] - mx0);
            s[n][2] = __expf(s[n][2] - mx1);
            s[n][3] = __expf(s[n][3] - mx1);
            sum0 += s[n][0] + s[n][1];
            sum1 += s[n][2] + s[n][3];
        }
        sum0 += __shfl_xor_sync(0xffffffffu, sum0, 1);
        sum0 += __shfl_xor_sync(0xffffffffu, sum0, 2);
        sum1 += __shfl_xor_sync(0xffffffffu, sum1, 1);
        sum1 += __shfl_xor_sync(0xffffffffu, sum1, 2);

        const float cf0 = __expf(m0 - mx0);
        const float cf1 = __expf(m1 - mx1);
        l0 = l0 * cf0 + sum0;  m0 = mx0;
        l1 = l1 * cf1 + sum1;  m1 = mx1;
#pragma unroll
        for (int n = 0; n < 8; n++) {
            o[n][0] *= cf0; o[n][1] *= cf0;
            o[n][2] *= cf1; o[n][3] *= cf1;
        }

        // ---- P -> smem (per-warp region of Qs), then PV mma ----
#pragma unroll
        for (int n = 0; n < 8; n++) {
            const int pr = (wm + lrow) * AT_LDQ + n * 8 + 2 * lcol;
            *(uint2*)&Qs[pr] = make_uint2(f2tf32(s[n][0]), f2tf32(s[n][1]));
            *(uint2*)&Qs[pr + 8 * AT_LDQ] = make_uint2(f2tf32(s[n][2]), f2tf32(s[n][3]));
        }
        __syncwarp();

#pragma unroll
        for (int ks = 0; ks < 8; ks++) {
            const int kk = ks * 8;
            const int pb = (wm + lrow) * AT_LDQ + kk + lcol;
            const uint32_t a0 = Qs[pb];
            const uint32_t a1 = Qs[pb + 8 * AT_LDQ];
            const uint32_t a2 = Qs[pb + 4];
            const uint32_t a3 = Qs[pb + 8 * AT_LDQ + 4];
#pragma unroll
            for (int n = 0; n < 8; n++) {
                const uint32_t b0 = Vs[(kk + lcol) * AT_LDV + n * 8 + lrow];
                const uint32_t b1 = Vs[(kk + 4 + lcol) * AT_LDV + n * 8 + lrow];
                mma_tf32_16x8x8(o[n][0], o[n][1], o[n][2], o[n][3],
                                a0, a1, a2, a3, b0, b1);
            }
        }
        __syncwarp();
    }

    // ---- normalize and store ----
    const float inv0 = 1.0f / l0;
    const float inv1 = 1.0f / l1;
    const int b_ = bh >> 4, h = bh & 15;
    const size_t rowbase0 = (size_t)(b_ * TT + r0g) * EE + h * HD;
    const size_t rowbase1 = (size_t)(b_ * TT + r1g) * EE + h * HD;
#pragma unroll
    for (int n = 0; n < 8; n++) {
        const int d = n * 8 + 2 * lcol;
        *(float2*)&g_AO[rowbase0 + d] = make_float2(o[n][0] * inv0, o[n][1] * inv0);
        *(float2*)&g_AO[rowbase1 + d] = make_float2(o[n][2] * inv1, o[n][3] * inv1);
    }
}

// ---------------------------------------------------------------------------
// Kernel 3: tf32 mma.sync output projection (unchanged — known correct)
// ---------------------------------------------------------------------------
#define PJ_LDA 36   // 32 + 4 pad (float4-aligned, conflict-free fragments)

__global__ __launch_bounds__(256, 1)
void proj_mma_kernel(const float* __restrict__ Wp,
                     const float* __restrict__ bp,
                     float* __restrict__ out) {
    __shared__ uint32_t As[128 * PJ_LDA];   // A tile, tf32 bits, [r][k]
    __shared__ uint32_t Bs[128 * PJ_LDA];   // B tile (=Wp rows), [n][k]

    const int tid  = threadIdx.x;
    const int wid  = tid >> 5;
    const int lane = tid & 31;
    const int row0 = blockIdx.x * 128;
    const int col0 = blockIdx.y * 128;

    const int warp_m = (wid & 1) * 64;   // 0 or 64
    const int warp_n = (wid >> 1) * 32;  // 0,32,64,96

    float c[4][4][4];   // [m16][n8][frag]
#pragma unroll
    for (int m = 0; m < 4; m++)
#pragma unroll
        for (int n = 0; n < 4; n++)
#pragma unroll
            for (int f = 0; f < 4; f++) c[m][n][f] = 0.f;

    const int lrow = lane >> 2;    // 0..7
    const int lcol = lane & 3;     // 0..3

    for (int kt = 0; kt < EE / 32; kt++) {
        const int k0 = kt * 32;
        __syncthreads();
        // stage A and B tiles (each 128x32 floats; 4 float4 per thread each)
#pragma unroll
        for (int it = 0; it < 4; it++) {
            const int lin = it * 1024 + tid * 4;   // 0..4095
            const int r = lin >> 5, cc = lin & 31;
            const float4 va = *(const float4*)&g_AO[(size_t)(row0 + r) * EE + k0 + cc];
            const float4 vb = *(const float4*)&Wp  [(size_t)(col0 + r) * EE + k0 + cc];
            *(uint4*)&As[r * PJ_LDA + cc] =
                make_uint4(f2tf32(va.x), f2tf32(va.y), f2tf32(va.z), f2tf32(va.w));
            *(uint4*)&Bs[r * PJ_LDA + cc] =
                make_uint4(f2tf32(vb.x), f2tf32(vb.y), f2tf32(vb.z), f2tf32(vb.w));
        }
        __syncthreads();

#pragma unroll
        for (int ks = 0; ks < 4; ks++) {
            const int kk = ks * 8;
            uint32_t a[4][4], b[4][2];
#pragma unroll
            for (int m = 0; m < 4; m++) {
                const int ar = warp_m + m * 16 + lrow;
                a[m][0] = As[ar * PJ_LDA + kk + lcol];
                a[m][1] = As[(ar + 8) * PJ_LDA + kk + lcol];
                a[m][2] = As[ar * PJ_LDA + kk + 4 + lcol];
                a[m][3] = As[(ar + 8) * PJ_LDA + kk + 4 + lcol];
            }
#pragma unroll
            for (int n = 0; n < 4; n++) {
                const int br = warp_n + n * 8 + lrow;
                b[n][0] = Bs[br * PJ_LDA + kk + lcol];
                b[n][1] = Bs[br * PJ_LDA + kk + 4 + lcol];
            }
#pragma unroll
            for (int m = 0; m < 4; m++)
#pragma unroll
                for (int n = 0; n < 4; n++)
                    mma_tf32_16x8x8(c[m][n][0], c[m][n][1], c[m][n][2], c[m][n][3],
                                    a[m][0], a[m][1], a[m][2], a[m][3],
                                    b[n][0], b[n][1]);
        }
    }

    // epilogue: c frag rows = lane/4 (+8), cols = 2*(lane%4) (+1)
#pragma unroll
    for (int m = 0; m < 4; m++) {
#pragma unroll
        for (int n = 0; n < 4; n++) {
            const int col = col0 + warp_n + n * 8 + 2 * lcol;
            const int r1  = row0 + warp_m + m * 16 + lrow;
            const float b0 = bp[col], b1 = bp[col + 1];
            float2 o0 = make_float2(c[m][n][0] + b0, c[m][n][1] + b1);
            float2 o1 = make_float2(c[m][n][2] + b0, c[m][n][3] + b1);
            *(float2*)&out[(size_t)r1 * EE + col]       = o0;
            *(float2*)&out[(size_t)(r1 + 8) * EE + col] = o1;
        }
    }
}

// ---------------------------------------------------------------------------
// Launch
// ---------------------------------------------------------------------------
extern "C" void kernel_launch(void* const* d_in, const int* in_sizes, int n_in,
                              void* d_out, int out_size) {
    const float* x  = (const float*)d_in[0];
    const float* Wq = (const float*)d_in[1];
    const float* bq = (const float*)d_in[2];
    const float* Wp = (const float*)d_in[3];
    const float* bp = (const float*)d_in[4];
    float* out = (float*)d_out;

    cudaFuncSetAttribute(qkv_mma_kernel,  cudaFuncAttributeMaxDynamicSharedMemorySize, QK_SMEM);
    cudaFuncSetAttribute(attn_mma_kernel, cudaFuncAttributeMaxDynamicSharedMemorySize, AT_SMEM);

    qkv_mma_kernel<<<dim3(BT / 128, HH), 256, QK_SMEM>>>(x, Wq, bq);
    attn_mma_kernel<<<dim3(TT / 64, BB * HH), 128, AT_SMEM>>>();
    proj_mma_kernel<<<dim3(BT / 128, EE / 128), 256>>>(Wp, bp, out);
}